// round 6
// baseline (speedup 1.0000x reference)
#include <cuda_runtime.h>
#include <cuda_fp16.h>

// Problem constants (from reference setup_inputs)
#define Bn 8
#define Hn 768
#define Wn 768
#define NPIX (Bn * Hn * Wn)          // 4,718,592
#define HWn (Hn * Wn)
#define PROP_TIME 24
#define GROUP 4                       // per-group working set ~66MB, L2-resident

// 8 fp16 weights per pixel, one 16B vector load
struct __align__(16) W8 { __half2 h[4]; };

// Scratch: __device__ globals (allocation-free per harness rules).
__device__ W8    g_wh[NPIX];          // ~75.5 MB total, 37.7 MB per group
__device__ float g_base[NPIX];        // ~19 MB
__device__ float g_bufA[NPIX];        // ~19 MB
__device__ float g_bufB[NPIX];        // ~19 MB

// 8-neighbor offsets (dy, dx), reference order
__constant__ int c_dy[8] = {-5, -1, 0, 0, 5, 1,  0,  0};
__constant__ int c_dx[8] = { 0,  0, 5, 1, 0, 0, -5, -1};

// ---------------------------------------------------------------------------
// Precompute: normalized affinity weights (fp16-rounded), folded base from the
// ROUNDED weights. mask px: w=0, base=raw.  else: base = (1 - sum(w)) * raw.
// ---------------------------------------------------------------------------
__global__ void precompute_kernel(const float* __restrict__ guid,
                                  const float* __restrict__ blur,
                                  const float* __restrict__ sparse)
{
    int i = blockIdx.x * blockDim.x + threadIdx.x;
    if (i >= NPIX) return;

    int x = i % Wn;
    int t = i / Wn;
    int y = t % Hn;
    int b = t / Hn;

    const float* gb = guid + (size_t)b * 8 * HWn;

    float w[8];
    float s = 0.0f;
#pragma unroll
    for (int c = 0; c < 8; ++c) {
        int yy = y + c_dy[c];
        int xx = x + c_dx[c];
        float v = 0.0f;
        if ((unsigned)yy < (unsigned)Hn && (unsigned)xx < (unsigned)Wn)
            v = gb[(size_t)c * HWn + yy * Wn + xx];
        w[c] = v;
        s += fabsf(v);
    }
    float inv = 1.0f / fmaxf(s, 1e-6f);
#pragma unroll
    for (int c = 0; c < 8; ++c) w[c] *= inv;

    float raw  = blur[i];
    bool  mask = sparse[i] > 0.0f;

    if (mask) {
#pragma unroll
        for (int c = 0; c < 8; ++c) w[c] = 0.0f;
    }

    W8 pack;
    float gs = 0.0f;
#pragma unroll
    for (int c = 0; c < 4; ++c) {
        __half2 h = __floats2half2_rn(w[2 * c], w[2 * c + 1]);
        pack.h[c] = h;
        float2 back = __half22float2(h);
        gs += back.x + back.y;
    }

    g_wh[i]   = pack;
    g_base[i] = mask ? raw : (1.0f - gs) * raw;
}

// ---------------------------------------------------------------------------
// One propagation step, 4 pixels per thread (aligned quad).
//   r_out[j] = base[j] + sum_c w_c[j] * r_in[neighbor_c of j]
// Vertical taps: 4x float4 (uniform row guards). Horizontal taps: 3x float4
// + 2 scalars composed into 16 tap values (fast path); guarded scalars at the
// image edge quads only.
// ---------------------------------------------------------------------------
__global__ void __launch_bounds__(384, 2) prop_kernel(const float* __restrict__ rin,
                                                      float* __restrict__ rout,
                                                      int b0)
{
    int x0 = (blockIdx.x * 32 + threadIdx.x) * 4;
    int y  = blockIdx.y * 12 + threadIdx.y;
    int b  = b0 + blockIdx.z;

    size_t boff = (size_t)b * HWn;
    const float* row = rin + boff + (size_t)y * Wn;
    size_t i = boff + (size_t)y * Wn + x0;

    // weights + base (L2-resident streams, skip L1)
    uint4 u0 = __ldcg(reinterpret_cast<const uint4*>(&g_wh[i]));
    uint4 u1 = __ldcg(reinterpret_cast<const uint4*>(&g_wh[i + 1]));
    uint4 u2 = __ldcg(reinterpret_cast<const uint4*>(&g_wh[i + 2]));
    uint4 u3 = __ldcg(reinterpret_cast<const uint4*>(&g_wh[i + 3]));
    float4 basev = __ldcg(reinterpret_cast<const float4*>(&g_base[i]));

    const float4 z4 = make_float4(0.f, 0.f, 0.f, 0.f);

    // vertical taps (uniform guards per thread)
    float4 up5 = (y >= 5)     ? __ldg(reinterpret_cast<const float4*>(row - 5 * Wn + x0)) : z4;
    float4 up1 = (y >= 1)     ? __ldg(reinterpret_cast<const float4*>(row - Wn + x0))     : z4;
    float4 dn5 = (y + 5 < Hn) ? __ldg(reinterpret_cast<const float4*>(row + 5 * Wn + x0)) : z4;
    float4 dn1 = (y + 1 < Hn) ? __ldg(reinterpret_cast<const float4*>(row + Wn + x0))     : z4;

    // horizontal taps
    float4 lf5v, lf1v, rt1v, rt5v;
    if (x0 >= 8 && x0 + 12 <= Wn) {
        float  sm5 = __ldg(row + x0 - 5);
        float4 vm  = __ldg(reinterpret_cast<const float4*>(row + x0 - 4));
        float4 vc  = __ldg(reinterpret_cast<const float4*>(row + x0));
        float4 vp  = __ldg(reinterpret_cast<const float4*>(row + x0 + 4));
        float  sp8 = __ldg(row + x0 + 8);
        lf5v = make_float4(sm5,  vm.x, vm.y, vm.z);
        lf1v = make_float4(vm.w, vc.x, vc.y, vc.z);
        rt1v = make_float4(vc.y, vc.z, vc.w, vp.x);
        rt5v = make_float4(vp.y, vp.z, vp.w, sp8);
    } else {
        float t[14];
#pragma unroll
        for (int k = 0; k < 14; ++k) {
            int xx = x0 - 5 + k;
            t[k] = ((unsigned)xx < (unsigned)Wn) ? __ldg(row + xx) : 0.0f;
        }
        lf5v = make_float4(t[0], t[1], t[2],  t[3]);
        lf1v = make_float4(t[4], t[5], t[6],  t[7]);
        rt1v = make_float4(t[6], t[7], t[8],  t[9]);
        rt5v = make_float4(t[10], t[11], t[12], t[13]);
    }

    float4 acc = basev;

    // pixel 0
    {
        float2 w01 = __half22float2(*reinterpret_cast<__half2*>(&u0.x));
        float2 w23 = __half22float2(*reinterpret_cast<__half2*>(&u0.y));
        float2 w45 = __half22float2(*reinterpret_cast<__half2*>(&u0.z));
        float2 w67 = __half22float2(*reinterpret_cast<__half2*>(&u0.w));
        acc.x = fmaf(w01.x, up5.x, acc.x);
        acc.x = fmaf(w01.y, up1.x, acc.x);
        acc.x = fmaf(w23.x, rt5v.x, acc.x);
        acc.x = fmaf(w23.y, rt1v.x, acc.x);
        acc.x = fmaf(w45.x, dn5.x, acc.x);
        acc.x = fmaf(w45.y, dn1.x, acc.x);
        acc.x = fmaf(w67.x, lf5v.x, acc.x);
        acc.x = fmaf(w67.y, lf1v.x, acc.x);
    }
    // pixel 1
    {
        float2 w01 = __half22float2(*reinterpret_cast<__half2*>(&u1.x));
        float2 w23 = __half22float2(*reinterpret_cast<__half2*>(&u1.y));
        float2 w45 = __half22float2(*reinterpret_cast<__half2*>(&u1.z));
        float2 w67 = __half22float2(*reinterpret_cast<__half2*>(&u1.w));
        acc.y = fmaf(w01.x, up5.y, acc.y);
        acc.y = fmaf(w01.y, up1.y, acc.y);
        acc.y = fmaf(w23.x, rt5v.y, acc.y);
        acc.y = fmaf(w23.y, rt1v.y, acc.y);
        acc.y = fmaf(w45.x, dn5.y, acc.y);
        acc.y = fmaf(w45.y, dn1.y, acc.y);
        acc.y = fmaf(w67.x, lf5v.y, acc.y);
        acc.y = fmaf(w67.y, lf1v.y, acc.y);
    }
    // pixel 2
    {
        float2 w01 = __half22float2(*reinterpret_cast<__half2*>(&u2.x));
        float2 w23 = __half22float2(*reinterpret_cast<__half2*>(&u2.y));
        float2 w45 = __half22float2(*reinterpret_cast<__half2*>(&u2.z));
        float2 w67 = __half22float2(*reinterpret_cast<__half2*>(&u2.w));
        acc.z = fmaf(w01.x, up5.z, acc.z);
        acc.z = fmaf(w01.y, up1.z, acc.z);
        acc.z = fmaf(w23.x, rt5v.z, acc.z);
        acc.z = fmaf(w23.y, rt1v.z, acc.z);
        acc.z = fmaf(w45.x, dn5.z, acc.z);
        acc.z = fmaf(w45.y, dn1.z, acc.z);
        acc.z = fmaf(w67.x, lf5v.z, acc.z);
        acc.z = fmaf(w67.y, lf1v.z, acc.z);
    }
    // pixel 3
    {
        float2 w01 = __half22float2(*reinterpret_cast<__half2*>(&u3.x));
        float2 w23 = __half22float2(*reinterpret_cast<__half2*>(&u3.y));
        float2 w45 = __half22float2(*reinterpret_cast<__half2*>(&u3.z));
        float2 w67 = __half22float2(*reinterpret_cast<__half2*>(&u3.w));
        acc.w = fmaf(w01.x, up5.w, acc.w);
        acc.w = fmaf(w01.y, up1.w, acc.w);
        acc.w = fmaf(w23.x, rt5v.w, acc.w);
        acc.w = fmaf(w23.y, rt1v.w, acc.w);
        acc.w = fmaf(w45.x, dn5.w, acc.w);
        acc.w = fmaf(w45.y, dn1.w, acc.w);
        acc.w = fmaf(w67.x, lf5v.w, acc.w);
        acc.w = fmaf(w67.y, lf1v.w, acc.w);
    }

    __stcg(reinterpret_cast<float4*>(&rout[i]), acc);
}

// ---------------------------------------------------------------------------
// Launch: precompute once; per 4-batch group run all 24 iterations
// back-to-back so that group's fp16 weights stay L2-resident (~66MB set).
// ---------------------------------------------------------------------------
extern "C" void kernel_launch(void* const* d_in, const int* in_sizes, int n_in,
                              void* d_out, int out_size)
{
    const float* guid   = (const float*)d_in[0];   // (B,8,H,W)
    const float* blur   = (const float*)d_in[1];   // (B,1,H,W)
    const float* sparse = (const float*)d_in[2];   // (B,1,H,W)
    float* out = (float*)d_out;                    // (B,1,H,W)

    float *bufA, *bufB;
    cudaGetSymbolAddress((void**)&bufA, g_bufA);
    cudaGetSymbolAddress((void**)&bufB, g_bufB);

    {
        const int threads = 256;
        const int blocks  = (NPIX + threads - 1) / threads;
        precompute_kernel<<<blocks, threads>>>(guid, blur, sparse);
    }

    dim3 blk(32, 12);                 // thread tile: 128 x 12
    dim3 grd(Wn / 128, Hn / 12, GROUP);

    for (int g = 0; g < Bn / GROUP; ++g) {
        int b0 = g * GROUP;
        const float* cur = blur;
        for (int it = 0; it < PROP_TIME; ++it) {
            float* dst;
            if (it == PROP_TIME - 1)      dst = out;
            else if ((it & 1) == 0)       dst = bufA;
            else                          dst = bufB;
            prop_kernel<<<grd, blk>>>(cur, dst, b0);
            cur = dst;
        }
    }
}

// round 7
// speedup vs baseline: 1.1563x; 1.1563x over previous
#include <cuda_runtime.h>
#include <cuda_fp16.h>

// Problem constants (from reference setup_inputs)
#define Bn 8
#define Hn 768
#define Wn 768
#define NPIX (Bn * Hn * Wn)          // 4,718,592
#define HWn (Hn * Wn)
#define PROP_TIME 24
#define GROUP 4                       // per-group working set ~66MB, L2-resident

// 8 fp16 weights per pixel, one 16B vector load
struct __align__(16) W8 { __half2 h[4]; };

// Scratch: __device__ globals (allocation-free per harness rules).
__device__ W8    g_wh[NPIX];          // ~75.5 MB total, 37.7 MB per group
__device__ float g_base[NPIX];        // ~19 MB
__device__ float g_bufA[NPIX];        // ~19 MB
__device__ float g_bufB[NPIX];        // ~19 MB

// 8-neighbor offsets (dy, dx), reference order
__constant__ int c_dy[8] = {-5, -1, 0, 0, 5, 1,  0,  0};
__constant__ int c_dx[8] = { 0,  0, 5, 1, 0, 0, -5, -1};

// ---------------------------------------------------------------------------
// Precompute: normalized affinity weights (fp16-rounded), folded base from the
// ROUNDED weights. mask px: w=0, base=raw.  else: base = (1 - sum(w)) * raw.
// ---------------------------------------------------------------------------
__global__ void precompute_kernel(const float* __restrict__ guid,
                                  const float* __restrict__ blur,
                                  const float* __restrict__ sparse)
{
    int i = blockIdx.x * blockDim.x + threadIdx.x;
    if (i >= NPIX) return;

    int x = i % Wn;
    int t = i / Wn;
    int y = t % Hn;
    int b = t / Hn;

    const float* gb = guid + (size_t)b * 8 * HWn;

    float w[8];
    float s = 0.0f;
#pragma unroll
    for (int c = 0; c < 8; ++c) {
        int yy = y + c_dy[c];
        int xx = x + c_dx[c];
        float v = 0.0f;
        if ((unsigned)yy < (unsigned)Hn && (unsigned)xx < (unsigned)Wn)
            v = gb[(size_t)c * HWn + yy * Wn + xx];
        w[c] = v;
        s += fabsf(v);
    }
    float inv = 1.0f / fmaxf(s, 1e-6f);
#pragma unroll
    for (int c = 0; c < 8; ++c) w[c] *= inv;

    float raw  = blur[i];
    bool  mask = sparse[i] > 0.0f;

    if (mask) {
#pragma unroll
        for (int c = 0; c < 8; ++c) w[c] = 0.0f;
    }

    W8 pack;
    float gs = 0.0f;
#pragma unroll
    for (int c = 0; c < 4; ++c) {
        __half2 h = __floats2half2_rn(w[2 * c], w[2 * c + 1]);
        pack.h[c] = h;
        float2 back = __half22float2(h);
        gs += back.x + back.y;
    }

    g_wh[i]   = pack;
    g_base[i] = mask ? raw : (1.0f - gs) * raw;
}

// ---------------------------------------------------------------------------
// One propagation step, 2 pixels per thread (aligned pair).
// Vertical taps: 4x float2 (uniform guards). Horizontal taps: 8 guarded
// scalars (L1 hits). Weights: 2x LDG.128; base: LDG.64; store: STG.64.
// ---------------------------------------------------------------------------
__global__ void __launch_bounds__(256, 5) prop_kernel(const float* __restrict__ rin,
                                                      float* __restrict__ rout,
                                                      int b0)
{
    int x0 = (blockIdx.x * 32 + threadIdx.x) * 2;
    int y  = blockIdx.y * 8 + threadIdx.y;
    int b  = b0 + blockIdx.z;

    size_t boff = (size_t)b * HWn;
    const float* row = rin + boff + (size_t)y * Wn;
    size_t i = boff + (size_t)y * Wn + x0;

    // weights + base (L2-resident streams, skip L1)
    uint4  u0    = __ldcg(reinterpret_cast<const uint4*>(&g_wh[i]));
    uint4  u1    = __ldcg(reinterpret_cast<const uint4*>(&g_wh[i + 1]));
    float2 basev = __ldcg(reinterpret_cast<const float2*>(&g_base[i]));

    const float2 z2 = make_float2(0.f, 0.f);

    // vertical taps (uniform guards per thread)
    float2 up5 = (y >= 5)     ? __ldg(reinterpret_cast<const float2*>(row - 5 * Wn + x0)) : z2;
    float2 up1 = (y >= 1)     ? __ldg(reinterpret_cast<const float2*>(row - Wn + x0))     : z2;
    float2 dn5 = (y + 5 < Hn) ? __ldg(reinterpret_cast<const float2*>(row + 5 * Wn + x0)) : z2;
    float2 dn1 = (y + 1 < Hn) ? __ldg(reinterpret_cast<const float2*>(row + Wn + x0))     : z2;

    // horizontal taps: x0-5, x0-4, x0-1, x0+1, x0+2, x0+5, x0+6  (+x0 itself)
    float hm5 = (x0 >= 5)     ? __ldg(row + x0 - 5) : 0.0f;
    float hm4 = (x0 >= 4)     ? __ldg(row + x0 - 4) : 0.0f;
    float hm1 = (x0 >= 1)     ? __ldg(row + x0 - 1) : 0.0f;
    float hc0 = __ldg(row + x0);
    float hp1 = __ldg(row + x0 + 1);                       // x0+1 <= 766 ok
    float hp2 = (x0 + 2 < Wn) ? __ldg(row + x0 + 2) : 0.0f;
    float hp5 = (x0 + 5 < Wn) ? __ldg(row + x0 + 5) : 0.0f;
    float hp6 = (x0 + 6 < Wn) ? __ldg(row + x0 + 6) : 0.0f;

    float2 acc = basev;

    // pixel 0 (x0): lf5=hm5 lf1=hm1 rt1=hp1 rt5=hp5
    {
        float2 w01 = __half22float2(*reinterpret_cast<__half2*>(&u0.x));
        float2 w23 = __half22float2(*reinterpret_cast<__half2*>(&u0.y));
        float2 w45 = __half22float2(*reinterpret_cast<__half2*>(&u0.z));
        float2 w67 = __half22float2(*reinterpret_cast<__half2*>(&u0.w));
        acc.x = fmaf(w01.x, up5.x, acc.x);
        acc.x = fmaf(w01.y, up1.x, acc.x);
        acc.x = fmaf(w23.x, hp5,   acc.x);
        acc.x = fmaf(w23.y, hp1,   acc.x);
        acc.x = fmaf(w45.x, dn5.x, acc.x);
        acc.x = fmaf(w45.y, dn1.x, acc.x);
        acc.x = fmaf(w67.x, hm5,   acc.x);
        acc.x = fmaf(w67.y, hm1,   acc.x);
    }
    // pixel 1 (x0+1): lf5=hm4 lf1=hc0 rt1=hp2 rt5=hp6
    {
        float2 w01 = __half22float2(*reinterpret_cast<__half2*>(&u1.x));
        float2 w23 = __half22float2(*reinterpret_cast<__half2*>(&u1.y));
        float2 w45 = __half22float2(*reinterpret_cast<__half2*>(&u1.z));
        float2 w67 = __half22float2(*reinterpret_cast<__half2*>(&u1.w));
        acc.y = fmaf(w01.x, up5.y, acc.y);
        acc.y = fmaf(w01.y, up1.y, acc.y);
        acc.y = fmaf(w23.x, hp6,   acc.y);
        acc.y = fmaf(w23.y, hp2,   acc.y);
        acc.y = fmaf(w45.x, dn5.y, acc.y);
        acc.y = fmaf(w45.y, dn1.y, acc.y);
        acc.y = fmaf(w67.x, hm4,   acc.y);
        acc.y = fmaf(w67.y, hc0,   acc.y);
    }

    __stcg(reinterpret_cast<float2*>(&rout[i]), acc);
}

// ---------------------------------------------------------------------------
// Launch: precompute once; per 4-batch group run all 24 iterations
// back-to-back so that group's fp16 weights stay L2-resident (~66MB set).
// ---------------------------------------------------------------------------
extern "C" void kernel_launch(void* const* d_in, const int* in_sizes, int n_in,
                              void* d_out, int out_size)
{
    const float* guid   = (const float*)d_in[0];   // (B,8,H,W)
    const float* blur   = (const float*)d_in[1];   // (B,1,H,W)
    const float* sparse = (const float*)d_in[2];   // (B,1,H,W)
    float* out = (float*)d_out;                    // (B,1,H,W)

    float *bufA, *bufB;
    cudaGetSymbolAddress((void**)&bufA, g_bufA);
    cudaGetSymbolAddress((void**)&bufB, g_bufB);

    {
        const int threads = 256;
        const int blocks  = (NPIX + threads - 1) / threads;
        precompute_kernel<<<blocks, threads>>>(guid, blur, sparse);
    }

    dim3 blk(32, 8);                  // thread tile: 64 x 8
    dim3 grd(Wn / 64, Hn / 8, GROUP);

    for (int g = 0; g < Bn / GROUP; ++g) {
        int b0 = g * GROUP;
        const float* cur = blur;
        for (int it = 0; it < PROP_TIME; ++it) {
            float* dst;
            if (it == PROP_TIME - 1)      dst = out;
            else if ((it & 1) == 0)       dst = bufA;
            else                          dst = bufB;
            prop_kernel<<<grd, blk>>>(cur, dst, b0);
            cur = dst;
        }
    }
}